// round 2
// baseline (speedup 1.0000x reference)
#include <cuda_runtime.h>
#include <math.h>

#define NDOM 4
#define SQRT2F 1.41421356237309515f
#define EPS_REEIG_F 1e-4f
#define EPS_VAR_F 1e-5f

#define MAXB 32768
#define NB_MAX 1024
#define WPB 8            // warps per block
#define MPW 4            // matrices per warp
#define MPB (WPB*MPW)    // 32 matrices per block

#define LD0 21           // padded leading dim for n=20
#define LD1 17           // padded leading dim for n=15
#define SWEEPS20 8
#define SWEEPS15 8

// ---------------- device scratch (static, allowed) ----------------
__device__ float g_V2[(size_t)MAXB * 400];   // eigenvectors of centered matrices
__device__ float g_lw2[(size_t)MAXB * 20];   // log-eigenvalues of centered matrices
__device__ float g_Y[(size_t)MAXB * 225];    // BiMap outputs
__device__ float g_partL[(size_t)NB_MAX * NDOM * 400];
__device__ float g_partCnt[NB_MAX * NDOM];
__device__ float g_partN[NB_MAX * NDOM];
__device__ float g_partLY[NB_MAX * 225];
__device__ float g_Ginv[NDOM * 400];
__device__ float g_scale[NDOM];
__device__ float g_Gb[225];

// ---------------- per-warp workspace ----------------
struct WarpWS {
    float A[420];
    float V[420];
    float cb[16];
    float sb[16];
    int   pb[16];
    int   qb[16];
    float aux[24];
};

// round-robin tournament pair (circle method), players 0..NS-1, NS even
__device__ __forceinline__ void pair_pq(int k, int r, int M, int& p, int& q) {
    p = (k == 0) ? 0 : (1 + (k - 1 + r) % M);
    q = 1 + (M - 1 - k + r) % M;
}

// Warp-cooperative two-sided Jacobi eigensolver for symmetric NxN in smem.
// On exit: diag(A) = eigenvalues, columns of V = eigenvectors (A0 = V diag Vt).
template<int N, int LDA, int SWEEPS>
__device__ void jacobi_eigh(WarpWS* w, int lane) {
    constexpr int NS = (N & 1) ? (N + 1) : N;   // scheduling size (dummy if odd)
    constexpr int M  = NS - 1;
    constexpr int NP = NS / 2;
    float* A = w->A;
    float* V = w->V;

    // V := I over NS x NS region; zero-pad dummy row/col of A when N odd
    for (int idx = lane; idx < NS * LDA; idx += 32) V[idx] = 0.0f;
    __syncwarp();
    for (int i = lane; i < NS; i += 32) V[i * LDA + i] = 1.0f;
    if (NS != N) {
        // zero dummy column and row of A
        for (int i = lane; i < NS; i += 32) {
            A[i * LDA + N] = 0.0f;
            A[N * LDA + i] = 0.0f;
        }
    }
    __syncwarp();

    for (int sw = 0; sw < SWEEPS; sw++) {
        for (int r = 0; r < M; r++) {
            // ---- rotation parameters for NP disjoint pairs ----
            if (lane < NP) {
                int p, q; pair_pq(lane, r, M, p, q);
                float c = 1.0f, s = 0.0f;
                float apq = A[p * LDA + q];
                if (fabsf(apq) > 1e-38f) {
                    float app = A[p * LDA + p];
                    float aqq = A[q * LDA + q];
                    float tau = (aqq - app) / (2.0f * apq);
                    float den = fabsf(tau) + sqrtf(1.0f + tau * tau);
                    float t = (tau >= 0.0f ? 1.0f : -1.0f) / den;  // den=inf -> t=0
                    c = rsqrtf(1.0f + t * t);
                    s = t * c;
                }
                w->cb[lane] = c; w->sb[lane] = s;
                w->pb[lane] = p; w->qb[lane] = q;
            }
            __syncwarp();
            // ---- column rotations on A and V (A<-A*J, V<-V*J) ----
            for (int idx = lane; idx < 2 * NP * NS; idx += 32) {
                int k = idx / (2 * NS);
                int rem = idx - k * 2 * NS;
                float* Mx = A; int i = rem;
                if (rem >= NS) { Mx = V; i = rem - NS; }
                int p = w->pb[k], q = w->qb[k];
                float c = w->cb[k], s = w->sb[k];
                float xp = Mx[i * LDA + p], xq = Mx[i * LDA + q];
                Mx[i * LDA + p] = c * xp - s * xq;
                Mx[i * LDA + q] = s * xp + c * xq;
            }
            __syncwarp();
            // ---- row rotations on A (A <- Jt*A) ----
            for (int idx = lane; idx < NP * NS; idx += 32) {
                int k = idx / NS;
                int j = idx - k * NS;
                int p = w->pb[k], q = w->qb[k];
                float c = w->cb[k], s = w->sb[k];
                float xp = A[p * LDA + j], xq = A[q * LDA + j];
                A[p * LDA + j] = c * xp - s * xq;
                A[q * LDA + j] = s * xp + c * xq;
            }
            __syncwarp();
        }
    }
}

// Out[i][j] = sum_k V[i][k] * fw[k] * V[j][k]
template<int N, int LDA>
__device__ __forceinline__ void spectral_recompose(const float* V, const float* fw,
                                                   float* Out, int lane) {
    for (int idx = lane; idx < N * N; idx += 32) {
        int i = idx / N, j = idx - i * N;
        float acc = 0.0f;
        #pragma unroll
        for (int k = 0; k < N; k++)
            acc = fmaf(V[i * LDA + k] * fw[k], V[j * LDA + k], acc);
        Out[i * LDA + j] = acc;
    }
}

// ============ K1: per-sample logm(X), per-domain sum of L + counts ============
__global__ void __launch_bounds__(256) k_logsum(const float* __restrict__ X,
                                                const int* __restrict__ dom, int B) {
    __shared__ float acc[NDOM * 400];
    __shared__ float accCnt[NDOM];
    __shared__ WarpWS ws[WPB];
    int tid = threadIdx.x, warp = tid >> 5, lane = tid & 31;
    for (int i = tid; i < NDOM * 400; i += 256) acc[i] = 0.0f;
    if (tid < NDOM) accCnt[tid] = 0.0f;
    __syncthreads();
    WarpWS* w = &ws[warp];
    for (int m = 0; m < MPW; m++) {
        int b = ((int)blockIdx.x * WPB + warp) * MPW + m;
        bool active = (b < B);
        int d = 0;
        if (active) {
            d = dom[b];
            const float* Xb = X + (size_t)b * 400;
            for (int idx = lane; idx < 400; idx += 32) {
                int i = idx / 20, j = idx - i * 20;
                w->A[i * LD0 + j] = Xb[idx];
            }
            __syncwarp();
            jacobi_eigh<20, LD0, SWEEPS20>(w, lane);
            if (lane < 20) w->aux[lane] = logf(w->A[lane * LD0 + lane]);
            __syncwarp();
            spectral_recompose<20, LD0>(w->V, w->aux, w->A, lane);  // L into A
            __syncwarp();
        }
        // deterministic serialized block accumulation
        for (int t = 0; t < WPB; t++) {
            if (warp == t && active) {
                float* dst = acc + d * 400;
                for (int idx = lane; idx < 400; idx += 32) {
                    int i = idx / 20, j = idx - i * 20;
                    dst[idx] += w->A[i * LD0 + j];
                }
                if (lane == 0) accCnt[d] += 1.0f;
            }
            __syncthreads();
        }
    }
    for (int idx = tid; idx < NDOM * 400; idx += 256)
        g_partL[(size_t)blockIdx.x * (NDOM * 400) + idx] = acc[idx];
    if (tid < NDOM) g_partCnt[blockIdx.x * NDOM + tid] = accCnt[tid];
}

// ============ K2: reduce partials -> meanL; Ginv[d] = V e^{-w/2} Vt ============
__global__ void __launch_bounds__(128) k_ginv(int NB) {
    __shared__ float meanL[NDOM * 400];
    __shared__ float cnt[NDOM];
    __shared__ WarpWS ws[4];
    int tid = threadIdx.x;
    for (int idx = tid; idx < NDOM * 400; idx += 128) {
        float s = 0.0f;
        for (int b = 0; b < NB; b++) s += g_partL[(size_t)b * (NDOM * 400) + idx];
        meanL[idx] = s;
    }
    if (tid < NDOM) {
        float c = 0.0f;
        for (int b = 0; b < NB; b++) c += g_partCnt[b * NDOM + tid];
        cnt[tid] = c;
    }
    __syncthreads();
    for (int idx = tid; idx < NDOM * 400; idx += 128) meanL[idx] /= cnt[idx / 400];
    __syncthreads();
    int warp = tid >> 5, lane = tid & 31;
    WarpWS* w = &ws[warp];
    int d = warp;  // 4 warps, one domain each
    for (int idx = lane; idx < 400; idx += 32) {
        int i = idx / 20, j = idx - i * 20;
        w->A[i * LD0 + j] = meanL[d * 400 + idx];
    }
    __syncwarp();
    jacobi_eigh<20, LD0, SWEEPS20>(w, lane);
    if (lane < 20) w->aux[lane] = expf(-0.5f * w->A[lane * LD0 + lane]);
    __syncwarp();
    for (int idx = lane; idx < 400; idx += 32) {
        int i = idx / 20, j = idx - i * 20;
        float a = 0.0f;
        #pragma unroll
        for (int k = 0; k < 20; k++)
            a = fmaf(w->V[i * LD0 + k] * w->aux[k], w->V[j * LD0 + k], a);
        g_Ginv[d * 400 + idx] = a;
    }
}

// ====== K3: M = sym(Gi X Gi), eigh -> store V,logw; per-domain sum ||logM||^2 ======
__global__ void __launch_bounds__(256) k_center(const float* __restrict__ X,
                                                const int* __restrict__ dom, int B) {
    __shared__ float Gi[NDOM * 400];
    __shared__ float nrmAcc[WPB][NDOM];
    __shared__ WarpWS ws[WPB];
    int tid = threadIdx.x, warp = tid >> 5, lane = tid & 31;
    for (int idx = tid; idx < NDOM * 400; idx += 256) Gi[idx] = g_Ginv[idx];
    if (tid < WPB * NDOM) ((float*)nrmAcc)[tid] = 0.0f;
    __syncthreads();
    WarpWS* w = &ws[warp];
    for (int m = 0; m < MPW; m++) {
        int b = ((int)blockIdx.x * WPB + warp) * MPW + m;
        if (b < B) {
            int d = dom[b];
            const float* G = Gi + d * 400;
            const float* Xb = X + (size_t)b * 400;
            for (int idx = lane; idx < 400; idx += 32) {
                int i = idx / 20, j = idx - i * 20;
                w->A[i * LD0 + j] = Xb[idx];
            }
            __syncwarp();
            // T = X*G into V buffer
            for (int idx = lane; idx < 400; idx += 32) {
                int i = idx / 20, j = idx - i * 20;
                float a = 0.0f;
                #pragma unroll
                for (int k = 0; k < 20; k++) a = fmaf(w->A[i * LD0 + k], G[k * 20 + j], a);
                w->V[i * LD0 + j] = a;
            }
            __syncwarp();
            // M = G*T into A
            for (int idx = lane; idx < 400; idx += 32) {
                int i = idx / 20, j = idx - i * 20;
                float a = 0.0f;
                #pragma unroll
                for (int k = 0; k < 20; k++) a = fmaf(G[i * 20 + k], w->V[k * LD0 + j], a);
                w->A[i * LD0 + j] = a;
            }
            __syncwarp();
            // symmetrize
            for (int idx = lane; idx < 400; idx += 32) {
                int i = idx / 20, j = idx - i * 20;
                if (i < j) {
                    float a = w->A[i * LD0 + j], bb = w->A[j * LD0 + i];
                    float mv = 0.5f * (a + bb);
                    w->A[i * LD0 + j] = mv;
                    w->A[j * LD0 + i] = mv;
                }
            }
            __syncwarp();
            jacobi_eigh<20, LD0, SWEEPS20>(w, lane);
            if (lane < 20) w->aux[lane] = logf(w->A[lane * LD0 + lane]);
            __syncwarp();
            float* gV = g_V2 + (size_t)b * 400;
            for (int idx = lane; idx < 400; idx += 32) {
                int i = idx / 20, j = idx - i * 20;
                gV[idx] = w->V[i * LD0 + j];
            }
            if (lane < 20) g_lw2[(size_t)b * 20 + lane] = w->aux[lane];
            float v = (lane < 20) ? w->aux[lane] * w->aux[lane] : 0.0f;
            #pragma unroll
            for (int off = 16; off; off >>= 1) v += __shfl_down_sync(0xffffffffu, v, off);
            if (lane == 0) nrmAcc[warp][d] += v;
        }
    }
    __syncthreads();
    if (tid == 0) {
        float sums[NDOM] = {0.f, 0.f, 0.f, 0.f};
        for (int t = 0; t < WPB; t++)
            for (int d = 0; d < NDOM; d++) sums[d] += nrmAcc[t][d];
        for (int d = 0; d < NDOM; d++) g_partN[blockIdx.x * NDOM + d] = sums[d];
    }
}

// ============ K4: scale[d] = s / sqrt(sig2 + eps) ============
__global__ void k_scale(const float* __restrict__ sptr, int NB) {
    int d = threadIdx.x;
    if (d < NDOM) {
        float nsum = 0.0f, csum = 0.0f;
        for (int b = 0; b < NB; b++) {
            nsum += g_partN[b * NDOM + d];
            csum += g_partCnt[b * NDOM + d];
        }
        float sig2 = nsum / csum;
        g_scale[d] = sptr[0] / sqrtf(sig2 + EPS_VAR_F);
    }
}

// ====== K5: Xn via eigenbasis reuse, Y = Wt Xn W, store Y, sum logm(Y) ======
__global__ void __launch_bounds__(256) k_bimap(const float* __restrict__ Wb,
                                               const int* __restrict__ dom, int B) {
    __shared__ float W[300];
    __shared__ float accLY[225];
    __shared__ WarpWS ws[WPB];
    int tid = threadIdx.x, warp = tid >> 5, lane = tid & 31;
    for (int i = tid; i < 300; i += 256) W[i] = Wb[i];
    for (int i = tid; i < 225; i += 256) accLY[i] = 0.0f;
    __syncthreads();
    WarpWS* w = &ws[warp];
    for (int m = 0; m < MPW; m++) {
        int b = ((int)blockIdx.x * WPB + warp) * MPW + m;
        bool active = (b < B);
        if (active) {
            int d = dom[b];
            float sc = g_scale[d];
            const float* gV = g_V2 + (size_t)b * 400;
            if (lane < 20) w->aux[lane] = expf(0.5f * sc * g_lw2[(size_t)b * 20 + lane]);
            __syncwarp();
            // Z = V * diag(e^{sc*lw/2}) into A buffer  (Xn = Z Zt)
            for (int idx = lane; idx < 400; idx += 32) {
                int i = idx / 20, k = idx - i * 20;
                w->A[i * LD0 + k] = gV[idx] * w->aux[k];
            }
            __syncwarp();
            // C = Wt Z (15x20) into V buffer
            for (int idx = lane; idx < 300; idx += 32) {
                int o = idx / 20, k = idx - o * 20;
                float a = 0.0f;
                #pragma unroll
                for (int i2 = 0; i2 < 20; i2++) a = fmaf(W[i2 * 15 + o], w->A[i2 * LD0 + k], a);
                w->V[o * LD0 + k] = a;
            }
            __syncwarp();
            // Y = C Ct (15x15) into A (ld=17) and to global
            float* gY = g_Y + (size_t)b * 225;
            for (int idx = lane; idx < 225; idx += 32) {
                int o = idx / 15, p = idx - o * 15;
                float a = 0.0f;
                #pragma unroll
                for (int k = 0; k < 20; k++) a = fmaf(w->V[o * LD0 + k], w->V[p * LD0 + k], a);
                w->A[o * LD1 + p] = a;
                gY[idx] = a;
            }
            __syncwarp();
            jacobi_eigh<15, LD1, SWEEPS15>(w, lane);
            if (lane < 15) w->aux[lane] = logf(w->A[lane * LD1 + lane]);
            __syncwarp();
            spectral_recompose<15, LD1>(w->V, w->aux, w->A, lane);  // LY into A
            __syncwarp();
        }
        for (int t = 0; t < WPB; t++) {
            if (warp == t && active) {
                for (int idx = lane; idx < 225; idx += 32) {
                    int i = idx / 15, j = idx - i * 15;
                    accLY[idx] += w->A[i * LD1 + j];
                }
            }
            __syncthreads();
        }
    }
    for (int idx = tid; idx < 225; idx += 256)
        g_partLY[(size_t)blockIdx.x * 225 + idx] = accLY[idx];
}

// ============ K6: meanLY -> Gb = V e^{-w/2} Vt ============
__global__ void __launch_bounds__(256) k_gb(int B, int NB) {
    __shared__ float meanLY[225];
    __shared__ WarpWS ws;
    int tid = threadIdx.x;
    if (tid < 225) {
        float s = 0.0f;
        for (int b = 0; b < NB; b++) s += g_partLY[(size_t)b * 225 + tid];
        meanLY[tid] = s / (float)B;
    }
    __syncthreads();
    if (tid < 32) {
        int lane = tid;
        for (int idx = lane; idx < 225; idx += 32) {
            int i = idx / 15, j = idx - i * 15;
            ws.A[i * LD1 + j] = meanLY[idx];
        }
        __syncwarp();
        jacobi_eigh<15, LD1, SWEEPS15>(&ws, lane);
        if (lane < 15) ws.aux[lane] = expf(-0.5f * ws.A[lane * LD1 + lane]);
        __syncwarp();
        for (int idx = lane; idx < 225; idx += 32) {
            int i = idx / 15, j = idx - i * 15;
            float a = 0.0f;
            #pragma unroll
            for (int k = 0; k < 15; k++)
                a = fmaf(ws.V[i * LD1 + k] * ws.aux[k], ws.V[j * LD1 + k], a);
            g_Gb[idx] = a;
        }
    }
}

// ====== K7: Yn = sym(Gb Y Gb), eigh, Lf=V log(max(w,eps)) Vt, vec, classifier ======
__global__ void __launch_bounds__(256) k_head(const float* __restrict__ Wl,
                                              float* __restrict__ out, int B) {
    __shared__ float Gb[225];
    __shared__ float W[480];
    __shared__ WarpWS ws[WPB];
    int tid = threadIdx.x, warp = tid >> 5, lane = tid & 31;
    for (int i = tid; i < 225; i += 256) Gb[i] = g_Gb[i];
    for (int i = tid; i < 480; i += 256) W[i] = Wl[i];
    __syncthreads();
    WarpWS* w = &ws[warp];
    for (int m = 0; m < MPW; m++) {
        int b = ((int)blockIdx.x * WPB + warp) * MPW + m;
        if (b >= B) continue;
        const float* gY = g_Y + (size_t)b * 225;
        for (int idx = lane; idx < 225; idx += 32) {
            int i = idx / 15, j = idx - i * 15;
            w->A[i * LD1 + j] = gY[idx];
        }
        __syncwarp();
        // T = Y*Gb into V buffer
        for (int idx = lane; idx < 225; idx += 32) {
            int i = idx / 15, j = idx - i * 15;
            float a = 0.0f;
            #pragma unroll
            for (int k = 0; k < 15; k++) a = fmaf(w->A[i * LD1 + k], Gb[k * 15 + j], a);
            w->V[i * LD1 + j] = a;
        }
        __syncwarp();
        // Yn = Gb*T into A
        for (int idx = lane; idx < 225; idx += 32) {
            int i = idx / 15, j = idx - i * 15;
            float a = 0.0f;
            #pragma unroll
            for (int k = 0; k < 15; k++) a = fmaf(Gb[i * 15 + k], w->V[k * LD1 + j], a);
            w->A[i * LD1 + j] = a;
        }
        __syncwarp();
        // symmetrize
        for (int idx = lane; idx < 225; idx += 32) {
            int i = idx / 15, j = idx - i * 15;
            if (i < j) {
                float a = w->A[i * LD1 + j], bb = w->A[j * LD1 + i];
                float mv = 0.5f * (a + bb);
                w->A[i * LD1 + j] = mv;
                w->A[j * LD1 + i] = mv;
            }
        }
        __syncwarp();
        jacobi_eigh<15, LD1, SWEEPS15>(w, lane);
        if (lane < 15) w->aux[lane] = logf(fmaxf(w->A[lane * LD1 + lane], EPS_REEIG_F));
        __syncwarp();
        // vec + classifier fused: out[c] = sum over half-vec entries
        float o0 = 0.f, o1 = 0.f, o2 = 0.f, o3 = 0.f;
        for (int idx = lane; idx < 120; idx += 32) {
            int i, j;
            float coef;
            if (idx < 15) { i = idx; j = idx; coef = 1.0f; }
            else {
                int t = idx - 15;
                int ii = 0;
                while (t >= 14 - ii) { t -= 14 - ii; ii++; }
                i = ii; j = ii + 1 + t; coef = SQRT2F;
            }
            float lf = 0.0f;
            #pragma unroll
            for (int k = 0; k < 15; k++)
                lf = fmaf(w->V[i * LD1 + k] * w->aux[k], w->V[j * LD1 + k], lf);
            float v = coef * lf;
            o0 = fmaf(v, W[0 * 120 + idx], o0);
            o1 = fmaf(v, W[1 * 120 + idx], o1);
            o2 = fmaf(v, W[2 * 120 + idx], o2);
            o3 = fmaf(v, W[3 * 120 + idx], o3);
        }
        #pragma unroll
        for (int off = 16; off; off >>= 1) {
            o0 += __shfl_down_sync(0xffffffffu, o0, off);
            o1 += __shfl_down_sync(0xffffffffu, o1, off);
            o2 += __shfl_down_sync(0xffffffffu, o2, off);
            o3 += __shfl_down_sync(0xffffffffu, o3, off);
        }
        if (lane == 0) {
            float* ob = out + (size_t)b * 4;
            ob[0] = o0; ob[1] = o1; ob[2] = o2; ob[3] = o3;
        }
    }
}

extern "C" void kernel_launch(void* const* d_in, const int* in_sizes, int n_in,
                              void* d_out, int out_size) {
    const float* X   = (const float*)d_in[0];
    const int*   dom = (const int*)d_in[1];
    const float* s   = (const float*)d_in[2];
    const float* Wb  = (const float*)d_in[3];
    const float* Wl  = (const float*)d_in[4];
    float* out = (float*)d_out;
    int B = in_sizes[0] / 400;
    if (B > MAXB) B = MAXB;
    int NB = (B + MPB - 1) / MPB;
    if (NB > NB_MAX) NB = NB_MAX;

    k_logsum<<<NB, 256>>>(X, dom, B);
    k_ginv<<<1, 128>>>(NB);
    k_center<<<NB, 256>>>(X, dom, B);
    k_scale<<<1, 32>>>(s, NB);
    k_bimap<<<NB, 256>>>(Wb, dom, B);
    k_gb<<<1, 256>>>(B, NB);
    k_head<<<NB, 256>>>(Wl, out, B);
}

// round 3
// speedup vs baseline: 1.5875x; 1.5875x over previous
#include <cuda_runtime.h>
#include <math.h>

#define NDOM 4
#define SQRT2F 1.41421356237309515f
#define EPS_REEIG_F 1e-4f
#define EPS_VAR_F 1e-5f

#define MAXB 32768
#define NB_MAX 1024
#define WPB 8            // warps per block
#define MPW 4            // matrices per warp
#define MPB (WPB*MPW)    // 32 matrices per block

#define LDC 20           // column stride (floats) for col-major matrices
#define SW20 6
#define SW15 6

// ---------------- device scratch (static, allowed) ----------------
__device__ float g_V2[(size_t)MAXB * 400];   // eigenvectors (col-major) of centered matrices
__device__ float g_lw2[(size_t)MAXB * 20];   // log-eigenvalues of centered matrices
__device__ float g_Y[(size_t)MAXB * 225];    // BiMap outputs
__device__ float g_partL[(size_t)NB_MAX * NDOM * 400];
__device__ float g_partCnt[NB_MAX * NDOM];
__device__ float g_partN[NB_MAX * NDOM];
__device__ float g_partLY[NB_MAX * 225];
__device__ float g_meanL[NDOM * 400];
__device__ float g_cnt[NDOM];
__device__ float g_Ginv[NDOM * 400];
__device__ float g_scale[NDOM];
__device__ float g_Gb[225];

// ---------------- per-warp workspace ----------------
struct WarpWS {
    __align__(16) float A[400];   // col-major, LDC=20
    __align__(16) float V[400];   // col-major, LDC=20
    __align__(16) float4 prm[12]; // (c, s, p, q) packed
    float aux[24];
};

// round-robin tournament pair (circle method), players 0..NS-1, NS even
__device__ __forceinline__ void pair_pq(int k, int r, int M, int& p, int& q) {
    p = (k == 0) ? 0 : (1 + (k - 1 + r) % M);
    q = 1 + (M - 1 - k + r) % M;
}

// Warp-cooperative two-sided Jacobi, column-major A (LDC), eigenvectors in V columns.
// N=15 uses NS=16 with a zero dummy row/col (caller must zero-pad A).
template<int N, int SWEEPS>
__device__ void jacobi_cm(WarpWS* w, int lane) {
    constexpr int NS  = (N + 1) & ~1;
    constexpr int M   = NS - 1;
    constexpr int NP  = NS / 2;
    constexpr int NV4 = NS / 4;   // NS divisible by 4 for 20, 16
    float* A = w->A;
    float* V = w->V;
    float4* prm = w->prm;

    #pragma unroll
    for (int t = 0; t < (NS * LDC + 31) / 32; t++) {
        int i = lane + 32 * t;
        if (i < NS * LDC) V[i] = 0.0f;
    }
    __syncwarp();
    if (lane < NS) V[lane * LDC + lane] = 1.0f;
    __syncwarp();

    for (int sw = 0; sw < SWEEPS; sw++)
    for (int r = 0; r < M; r++) {
        // ---- rotation parameters ----
        if (lane < NP) {
            int p, q; pair_pq(lane, r, M, p, q);
            float apq = A[q * LDC + p];
            float c = 1.0f, s = 0.0f;
            if (fabsf(apq) > 1e-38f) {
                float app = A[p * LDC + p];
                float aqq = A[q * LDC + q];
                float tau = (aqq - app) / (2.0f * apq);
                float den = fabsf(tau) + sqrtf(fmaf(tau, tau, 1.0f));
                float tt  = (tau >= 0.0f ? 1.0f : -1.0f) / den;
                c = rsqrtf(fmaf(tt, tt, 1.0f));
                s = tt * c;
            }
            prm[lane] = make_float4(c, s, __int_as_float(p), __int_as_float(q));
        }
        __syncwarp();
        // ---- column rotations on A and V (vectorized, staged) ----
        {
            constexpr int NIT = (2 * NP * NV4 + 31) / 32;
            float4 xp[NIT], xq[NIT];
            #pragma unroll
            for (int t = 0; t < NIT; t++) {
                int idx = lane + 32 * t;
                if (idx < 2 * NP * NV4) {
                    int k = idx / (2 * NV4);
                    int rem = idx - k * (2 * NV4);
                    float* Mx = (rem < NV4) ? A : V;
                    int ch = (rem < NV4) ? rem : rem - NV4;
                    float4 pr = prm[k];
                    int p = __float_as_int(pr.z), q = __float_as_int(pr.w);
                    xp[t] = *(reinterpret_cast<float4*>(Mx + p * LDC) + ch);
                    xq[t] = *(reinterpret_cast<float4*>(Mx + q * LDC) + ch);
                }
            }
            #pragma unroll
            for (int t = 0; t < NIT; t++) {
                int idx = lane + 32 * t;
                if (idx < 2 * NP * NV4) {
                    int k = idx / (2 * NV4);
                    int rem = idx - k * (2 * NV4);
                    float* Mx = (rem < NV4) ? A : V;
                    int ch = (rem < NV4) ? rem : rem - NV4;
                    float4 pr = prm[k];
                    int p = __float_as_int(pr.z), q = __float_as_int(pr.w);
                    float c = pr.x, s = pr.y;
                    float4 a = xp[t], b = xq[t], np, nq;
                    np.x = fmaf(c, a.x, -s * b.x); nq.x = fmaf(s, a.x, c * b.x);
                    np.y = fmaf(c, a.y, -s * b.y); nq.y = fmaf(s, a.y, c * b.y);
                    np.z = fmaf(c, a.z, -s * b.z); nq.z = fmaf(s, a.z, c * b.z);
                    np.w = fmaf(c, a.w, -s * b.w); nq.w = fmaf(s, a.w, c * b.w);
                    *(reinterpret_cast<float4*>(Mx + p * LDC) + ch) = np;
                    *(reinterpret_cast<float4*>(Mx + q * LDC) + ch) = nq;
                }
            }
        }
        __syncwarp();
        // ---- row rotations on A (staged) ----
        {
            constexpr int NIT2 = (NP * NS + 31) / 32;
            float xp[NIT2], xq[NIT2];
            #pragma unroll
            for (int t = 0; t < NIT2; t++) {
                int idx = lane + 32 * t;
                if (idx < NP * NS) {
                    int k = idx / NS;
                    int j = idx - k * NS;
                    float4 pr = prm[k];
                    int p = __float_as_int(pr.z), q = __float_as_int(pr.w);
                    xp[t] = A[j * LDC + p];
                    xq[t] = A[j * LDC + q];
                }
            }
            #pragma unroll
            for (int t = 0; t < NIT2; t++) {
                int idx = lane + 32 * t;
                if (idx < NP * NS) {
                    int k = idx / NS;
                    int j = idx - k * NS;
                    float4 pr = prm[k];
                    int p = __float_as_int(pr.z), q = __float_as_int(pr.w);
                    float c = pr.x, s = pr.y;
                    A[j * LDC + p] = fmaf(c, xp[t], -s * xq[t]);
                    A[j * LDC + q] = fmaf(s, xp[t],  c * xq[t]);
                }
            }
        }
        __syncwarp();
    }
}

// Out[i*N+j] = sum_k V[:,k][i] * fw[k] * V[:,k][j]   (V col-major, LDC)
template<int N>
__device__ __forceinline__ void recompose_cm(const float* V, const float* fw,
                                             float* Out, int lane) {
    #pragma unroll
    for (int t = 0; t < (N * N + 31) / 32; t++) {
        int idx = lane + 32 * t;
        if (idx < N * N) {
            int i = idx / N, j = idx - i * N;
            float acc = 0.0f;
            #pragma unroll
            for (int k = 0; k < N; k++)
                acc = fmaf(V[k * LDC + i] * fw[k], V[k * LDC + j], acc);
            Out[idx] = acc;
        }
    }
}

// ============ K1: per-sample logm(X), per-domain sum of L + counts ============
__global__ void __launch_bounds__(256) k_logsum(const float* __restrict__ X,
                                                const int* __restrict__ dom, int B) {
    __shared__ float acc[NDOM * 400];
    __shared__ float accCnt[NDOM];
    __shared__ WarpWS ws[WPB];
    int tid = threadIdx.x, warp = tid >> 5, lane = tid & 31;
    for (int i = tid; i < NDOM * 400; i += 256) acc[i] = 0.0f;
    if (tid < NDOM) accCnt[tid] = 0.0f;
    __syncthreads();
    WarpWS* w = &ws[warp];
    for (int m = 0; m < MPW; m++) {
        int b = ((int)blockIdx.x * WPB + warp) * MPW + m;
        bool active = (b < B);
        int d = 0;
        if (active) {
            d = dom[b];
            const float* Xb = X + (size_t)b * 400;
            for (int idx = lane; idx < 400; idx += 32) w->A[idx] = Xb[idx];  // symmetric
            __syncwarp();
            jacobi_cm<20, SW20>(w, lane);
            if (lane < 20) w->aux[lane] = logf(w->A[lane * LDC + lane]);
            __syncwarp();
            recompose_cm<20>(w->V, w->aux, w->A, lane);   // L (plain) into A
            __syncwarp();
        }
        for (int t = 0; t < WPB; t++) {
            if (warp == t && active) {
                float* dst = acc + d * 400;
                for (int idx = lane; idx < 400; idx += 32) dst[idx] += w->A[idx];
                if (lane == 0) accCnt[d] += 1.0f;
            }
            __syncthreads();
        }
    }
    for (int idx = tid; idx < NDOM * 400; idx += 256)
        g_partL[(size_t)blockIdx.x * (NDOM * 400) + idx] = acc[idx];
    if (tid < NDOM) g_partCnt[blockIdx.x * NDOM + tid] = accCnt[tid];
}

// ===== K1b: parallel reduce of g_partL over blocks (1600 outputs) =====
__global__ void __launch_bounds__(256) kr_meanL(int NB) {
    int gw = blockIdx.x * 8 + (threadIdx.x >> 5);   // 400 warps
    int lane = threadIdx.x & 31;
    #pragma unroll
    for (int o = 0; o < 4; o++) {
        int out = gw * 4 + o;
        float s = 0.0f;
        for (int b = lane; b < NB; b += 32)
            s += g_partL[(size_t)b * (NDOM * 400) + out];
        #pragma unroll
        for (int off = 16; off; off >>= 1) s += __shfl_down_sync(0xffffffffu, s, off);
        if (lane == 0) g_meanL[out] = s;
    }
}

// ============ K2: counts + Ginv[d] = V e^{-w/2} Vt ============
__global__ void __launch_bounds__(128) k_ginv(int NB) {
    __shared__ WarpWS ws[4];
    int tid = threadIdx.x, warp = tid >> 5, lane = tid & 31;
    int d = warp;
    float csum = 0.0f;
    for (int b = lane; b < NB; b += 32) csum += g_partCnt[b * NDOM + d];
    #pragma unroll
    for (int off = 16; off; off >>= 1) csum += __shfl_down_sync(0xffffffffu, csum, off);
    float cnt = __shfl_sync(0xffffffffu, csum, 0);
    if (lane == 0) g_cnt[d] = cnt;
    WarpWS* w = &ws[warp];
    float inv = 1.0f / cnt;
    for (int idx = lane; idx < 400; idx += 32)
        w->A[idx] = g_meanL[d * 400 + idx] * inv;   // symmetric
    __syncwarp();
    jacobi_cm<20, SW20>(w, lane);
    if (lane < 20) w->aux[lane] = expf(-0.5f * w->A[lane * LDC + lane]);
    __syncwarp();
    recompose_cm<20>(w->V, w->aux, g_Ginv + d * 400, lane);
}

// ====== K3: M = sym(Gi X Gi), eigh -> store V,logw; per-domain sum ||logM||^2 ======
__global__ void __launch_bounds__(256) k_center(const float* __restrict__ X,
                                                const int* __restrict__ dom, int B) {
    __shared__ float Gi[NDOM * 400];
    __shared__ float nrmAcc[WPB][NDOM];
    __shared__ WarpWS ws[WPB];
    int tid = threadIdx.x, warp = tid >> 5, lane = tid & 31;
    for (int idx = tid; idx < NDOM * 400; idx += 256) Gi[idx] = g_Ginv[idx];
    if (tid < WPB * NDOM) ((float*)nrmAcc)[tid] = 0.0f;
    __syncthreads();
    WarpWS* w = &ws[warp];
    for (int m = 0; m < MPW; m++) {
        int b = ((int)blockIdx.x * WPB + warp) * MPW + m;
        if (b < B) {
            int d = dom[b];
            const float* G = Gi + d * 400;
            const float* Xb = X + (size_t)b * 400;
            for (int idx = lane; idx < 400; idx += 32) w->A[idx] = Xb[idx];  // plain X
            __syncwarp();
            // T1 = G * X into V (plain)
            for (int idx = lane; idx < 400; idx += 32) {
                int i = idx / 20, j = idx - i * 20;
                float a = 0.0f;
                #pragma unroll
                for (int k = 0; k < 20; k++) a = fmaf(G[i * 20 + k], w->A[k * 20 + j], a);
                w->V[idx] = a;
            }
            __syncwarp();
            // M = T1 * G into A (col-major: A[j*LDC+i] = M[i][j])
            for (int idx = lane; idx < 400; idx += 32) {
                int i = idx / 20, j = idx - i * 20;
                float a = 0.0f;
                #pragma unroll
                for (int k = 0; k < 20; k++) a = fmaf(w->V[i * 20 + k], G[k * 20 + j], a);
                w->A[j * LDC + i] = a;
            }
            __syncwarp();
            // symmetrize
            for (int idx = lane; idx < 400; idx += 32) {
                int i = idx / 20, j = idx - i * 20;
                if (i < j) {
                    float a = w->A[j * LDC + i], bb = w->A[i * LDC + j];
                    float mv = 0.5f * (a + bb);
                    w->A[j * LDC + i] = mv;
                    w->A[i * LDC + j] = mv;
                }
            }
            __syncwarp();
            jacobi_cm<20, SW20>(w, lane);
            if (lane < 20) w->aux[lane] = logf(w->A[lane * LDC + lane]);
            __syncwarp();
            float* gV = g_V2 + (size_t)b * 400;
            for (int idx = lane; idx < 400; idx += 32) gV[idx] = w->V[idx];  // col-major
            if (lane < 20) g_lw2[(size_t)b * 20 + lane] = w->aux[lane];
            float v = (lane < 20) ? w->aux[lane] * w->aux[lane] : 0.0f;
            #pragma unroll
            for (int off = 16; off; off >>= 1) v += __shfl_down_sync(0xffffffffu, v, off);
            if (lane == 0) nrmAcc[warp][d] += v;
        }
    }
    __syncthreads();
    if (tid == 0) {
        float sums[NDOM] = {0.f, 0.f, 0.f, 0.f};
        for (int t = 0; t < WPB; t++)
            for (int d = 0; d < NDOM; d++) sums[d] += nrmAcc[t][d];
        for (int d = 0; d < NDOM; d++) g_partN[blockIdx.x * NDOM + d] = sums[d];
    }
}

// ============ K4: scale[d] = s / sqrt(sig2 + eps) ============
__global__ void __launch_bounds__(128) k_scale(const float* __restrict__ sptr, int NB) {
    int warp = threadIdx.x >> 5, lane = threadIdx.x & 31;
    int d = warp;
    float nsum = 0.0f;
    for (int b = lane; b < NB; b += 32) nsum += g_partN[b * NDOM + d];
    #pragma unroll
    for (int off = 16; off; off >>= 1) nsum += __shfl_down_sync(0xffffffffu, nsum, off);
    if (lane == 0) {
        float sig2 = nsum / g_cnt[d];
        g_scale[d] = sptr[0] / sqrtf(sig2 + EPS_VAR_F);
    }
}

// ====== K5: Xn via eigenbasis reuse, Y = Wt Xn W, store Y, sum logm(Y) ======
__global__ void __launch_bounds__(256) k_bimap(const float* __restrict__ Wb,
                                               const int* __restrict__ dom, int B) {
    __shared__ float W[300];
    __shared__ float accLY[225];
    __shared__ WarpWS ws[WPB];
    int tid = threadIdx.x, warp = tid >> 5, lane = tid & 31;
    for (int i = tid; i < 300; i += 256) W[i] = Wb[i];
    for (int i = tid; i < 225; i += 256) accLY[i] = 0.0f;
    __syncthreads();
    WarpWS* w = &ws[warp];
    for (int m = 0; m < MPW; m++) {
        int b = ((int)blockIdx.x * WPB + warp) * MPW + m;
        bool active = (b < B);
        if (active) {
            int d = dom[b];
            float sc = g_scale[d];
            const float* gV = g_V2 + (size_t)b * 400;
            if (lane < 20) w->aux[lane] = expf(0.5f * sc * g_lw2[(size_t)b * 20 + lane]);
            __syncwarp();
            // Z = V * diag(e^{sc*lw/2}) (col-major) into A
            for (int idx = lane; idx < 400; idx += 32)
                w->A[idx] = gV[idx] * w->aux[idx / 20];
            __syncwarp();
            // C = Wt Z (15x20) into V: V[o*20+k]
            for (int idx = lane; idx < 300; idx += 32) {
                int o = idx / 20, k = idx - o * 20;
                float a = 0.0f;
                #pragma unroll
                for (int i2 = 0; i2 < 20; i2++)
                    a = fmaf(W[i2 * 15 + o], w->A[k * 20 + i2], a);
                w->V[o * 20 + k] = a;
            }
            __syncwarp();
            // zero A (16x20 region) for padded eigh
            for (int idx = lane; idx < 320; idx += 32) w->A[idx] = 0.0f;
            __syncwarp();
            // Y = C Ct into A (col-major) + global
            float* gY = g_Y + (size_t)b * 225;
            for (int idx = lane; idx < 225; idx += 32) {
                int o = idx / 15, p = idx - o * 15;
                float a = 0.0f;
                #pragma unroll
                for (int k = 0; k < 20; k++)
                    a = fmaf(w->V[o * 20 + k], w->V[p * 20 + k], a);
                w->A[p * LDC + o] = a;
                gY[idx] = a;
            }
            __syncwarp();
            jacobi_cm<15, SW15>(w, lane);
            if (lane < 15) w->aux[lane] = logf(w->A[lane * LDC + lane]);
            __syncwarp();
            recompose_cm<15>(w->V, w->aux, w->A, lane);   // LY plain into A
            __syncwarp();
        }
        for (int t = 0; t < WPB; t++) {
            if (warp == t && active) {
                for (int idx = lane; idx < 225; idx += 32) accLY[idx] += w->A[idx];
            }
            __syncthreads();
        }
    }
    for (int idx = tid; idx < 225; idx += 256)
        g_partLY[(size_t)blockIdx.x * 225 + idx] = accLY[idx];
}

// ============ K6: meanLY -> Gb = V e^{-w/2} Vt ============
__global__ void __launch_bounds__(256) k_gb(int B, int NB) {
    __shared__ float meanLY[225];
    __shared__ WarpWS ws0;
    int tid = threadIdx.x, warp = tid >> 5, lane = tid & 31;
    float invB = 1.0f / (float)B;
    for (int out = warp; out < 225; out += 8) {
        float s = 0.0f;
        for (int b = lane; b < NB; b += 32) s += g_partLY[(size_t)b * 225 + out];
        #pragma unroll
        for (int off = 16; off; off >>= 1) s += __shfl_down_sync(0xffffffffu, s, off);
        if (lane == 0) meanLY[out] = s * invB;
    }
    __syncthreads();
    if (warp == 0) {
        for (int idx = lane; idx < 320; idx += 32) ws0.A[idx] = 0.0f;
        __syncwarp();
        for (int idx = lane; idx < 225; idx += 32) {
            int i = idx / 15, j = idx - i * 15;
            ws0.A[j * LDC + i] = meanLY[idx];
        }
        __syncwarp();
        jacobi_cm<15, SW15>(&ws0, lane);
        if (lane < 15) ws0.aux[lane] = expf(-0.5f * ws0.A[lane * LDC + lane]);
        __syncwarp();
        recompose_cm<15>(ws0.V, ws0.aux, g_Gb, lane);
    }
}

// ====== K7: Yn = sym(Gb Y Gb), eigh, Lf=V log(max(w,eps)) Vt, vec, classifier ======
__global__ void __launch_bounds__(256) k_head(const float* __restrict__ Wl,
                                              float* __restrict__ out, int B) {
    __shared__ float Gb[225];
    __shared__ float W[480];
    __shared__ WarpWS ws[WPB];
    int tid = threadIdx.x, warp = tid >> 5, lane = tid & 31;
    for (int i = tid; i < 225; i += 256) Gb[i] = g_Gb[i];
    for (int i = tid; i < 480; i += 256) W[i] = Wl[i];
    __syncthreads();
    WarpWS* w = &ws[warp];
    for (int m = 0; m < MPW; m++) {
        int b = ((int)blockIdx.x * WPB + warp) * MPW + m;
        if (b >= B) continue;
        const float* gY = g_Y + (size_t)b * 225;
        for (int idx = lane; idx < 225; idx += 32) w->A[idx] = gY[idx];   // Y plain
        __syncwarp();
        // T = Y * Gb into V (plain 15x15)
        for (int idx = lane; idx < 225; idx += 32) {
            int i = idx / 15, j = idx - i * 15;
            float a = 0.0f;
            #pragma unroll
            for (int k = 0; k < 15; k++) a = fmaf(w->A[i * 15 + k], Gb[k * 15 + j], a);
            w->V[idx] = a;
        }
        __syncwarp();
        for (int idx = lane; idx < 320; idx += 32) w->A[idx] = 0.0f;
        __syncwarp();
        // M = Gb * T into A (col-major)
        for (int idx = lane; idx < 225; idx += 32) {
            int i = idx / 15, j = idx - i * 15;
            float a = 0.0f;
            #pragma unroll
            for (int k = 0; k < 15; k++) a = fmaf(Gb[i * 15 + k], w->V[k * 15 + j], a);
            w->A[j * LDC + i] = a;
        }
        __syncwarp();
        // symmetrize
        for (int idx = lane; idx < 225; idx += 32) {
            int i = idx / 15, j = idx - i * 15;
            if (i < j) {
                float a = w->A[j * LDC + i], bb = w->A[i * LDC + j];
                float mv = 0.5f * (a + bb);
                w->A[j * LDC + i] = mv;
                w->A[i * LDC + j] = mv;
            }
        }
        __syncwarp();
        jacobi_cm<15, SW15>(w, lane);
        if (lane < 15) w->aux[lane] = logf(fmaxf(w->A[lane * LDC + lane], EPS_REEIG_F));
        __syncwarp();
        // vec + classifier fused
        float o0 = 0.f, o1 = 0.f, o2 = 0.f, o3 = 0.f;
        for (int idx = lane; idx < 120; idx += 32) {
            int i, j;
            float coef;
            if (idx < 15) { i = idx; j = idx; coef = 1.0f; }
            else {
                int t = idx - 15;
                int ii = 0;
                while (t >= 14 - ii) { t -= 14 - ii; ii++; }
                i = ii; j = ii + 1 + t; coef = SQRT2F;
            }
            float lf = 0.0f;
            #pragma unroll
            for (int k = 0; k < 15; k++)
                lf = fmaf(w->V[k * LDC + i] * w->aux[k], w->V[k * LDC + j], lf);
            float v = coef * lf;
            o0 = fmaf(v, W[0 * 120 + idx], o0);
            o1 = fmaf(v, W[1 * 120 + idx], o1);
            o2 = fmaf(v, W[2 * 120 + idx], o2);
            o3 = fmaf(v, W[3 * 120 + idx], o3);
        }
        #pragma unroll
        for (int off = 16; off; off >>= 1) {
            o0 += __shfl_down_sync(0xffffffffu, o0, off);
            o1 += __shfl_down_sync(0xffffffffu, o1, off);
            o2 += __shfl_down_sync(0xffffffffu, o2, off);
            o3 += __shfl_down_sync(0xffffffffu, o3, off);
        }
        if (lane == 0) {
            float* ob = out + (size_t)b * 4;
            ob[0] = o0; ob[1] = o1; ob[2] = o2; ob[3] = o3;
        }
    }
}

extern "C" void kernel_launch(void* const* d_in, const int* in_sizes, int n_in,
                              void* d_out, int out_size) {
    const float* X   = (const float*)d_in[0];
    const int*   dom = (const int*)d_in[1];
    const float* s   = (const float*)d_in[2];
    const float* Wb  = (const float*)d_in[3];
    const float* Wl  = (const float*)d_in[4];
    float* out = (float*)d_out;
    int B = in_sizes[0] / 400;
    if (B > MAXB) B = MAXB;
    int NB = (B + MPB - 1) / MPB;
    if (NB > NB_MAX) NB = NB_MAX;

    k_logsum<<<NB, 256>>>(X, dom, B);
    kr_meanL<<<50, 256>>>(NB);
    k_ginv<<<1, 128>>>(NB);
    k_center<<<NB, 256>>>(X, dom, B);
    k_scale<<<1, 128>>>(s, NB);
    k_bimap<<<NB, 256>>>(Wb, dom, B);
    k_gb<<<1, 256>>>(B, NB);
    k_head<<<NB, 256>>>(Wl, out, B);
}

// round 4
// speedup vs baseline: 2.5026x; 1.5764x over previous
#include <cuda_runtime.h>
#include <math.h>

#define NDOM 4
#define SQRT2F 1.41421356237309515f
#define EPS_REEIG_F 1e-4f
#define EPS_VAR_F 1e-5f

#define MAXB 32768
#define NB_MAX 1024
#define WPB 8            // warps per block
#define MPW 4            // matrices per warp
#define MPB (WPB*MPW)    // 32 matrices per block

#define LDC 20           // column stride (floats) for col-major matrices
#define SW20 5
#define SW15 5
#define SW_SMALL 7

// ---------------- device scratch (static, allowed) ----------------
__device__ float g_V2[(size_t)MAXB * 400];   // eigenvectors (col-major) of centered matrices
__device__ float g_lw2[(size_t)MAXB * 20];   // log-eigenvalues of centered matrices
__device__ float g_Y[(size_t)MAXB * 225];    // BiMap outputs
__device__ float g_partL[(size_t)NB_MAX * NDOM * 400];
__device__ float g_partCnt[NB_MAX * NDOM];
__device__ float g_partN[NB_MAX * NDOM];
__device__ float g_partLY[NB_MAX * 225];
__device__ float g_meanL[NDOM * 400];
__device__ float g_cnt[NDOM];
__device__ float g_Ginv[NDOM * 400];
__device__ float g_scale[NDOM];
__device__ float g_Gb[225];

// ---------------- per-warp workspace ----------------
struct WarpWS {
    __align__(16) float A[400];   // col-major, LDC=20
    __align__(16) float V[400];   // col-major, LDC=20
    __align__(16) float4 prm[12]; // (c, s, p, q) packed
    float aux[24];
};

// round-robin tournament pair (circle method), players 0..NS-1, NS even
__device__ __forceinline__ void pair_pq(int k, int r, int M, int& p, int& q) {
    p = (k == 0) ? 0 : (1 + (k - 1 + r) % M);
    q = 1 + (M - 1 - k + r) % M;
}

// Warp-cooperative two-sided Jacobi, column-major A (stride LDC), V columns = eigenvectors.
// Single-pass 2x2 tile update: tiles over (pair_i, pair_j) are disjoint -> no staging.
// N odd uses NS=N+1 with a zero dummy row/col (caller zero-pads A); dummy stays exactly
// zero (its rotations are identity), eigenvalue 0 stays at index N.
template<int N, int SWEEPS>
__device__ void jacobi_cm(WarpWS* w, int lane) {
    constexpr int NS = (N + 1) & ~1;
    constexpr int M  = NS - 1;
    constexpr int NP = NS / 2;
    constexpr int NT = NP * NP;
    constexpr int CH = LDC / 4;   // float4 chunks per column (rows 16..19 are zero pad ok)
    float* A = w->A;
    float* V = w->V;
    float4* prm = w->prm;

    for (int i = lane; i < NS * LDC; i += 32) V[i] = 0.0f;
    __syncwarp();
    if (lane < NS) V[lane * LDC + lane] = 1.0f;
    __syncwarp();

    for (int sw = 0; sw < SWEEPS; sw++)
    for (int r = 0; r < M; r++) {
        // ---- rotation parameters (NP disjoint pairs) ----
        if (lane < NP) {
            int p, q; pair_pq(lane, r, M, p, q);
            float apq = A[q * LDC + p];
            float c = 1.0f, s = 0.0f;
            if (fabsf(apq) > 1e-38f) {
                float app = A[p * LDC + p];
                float aqq = A[q * LDC + q];
                float tau = (aqq - app) / (2.0f * apq);
                float den = fabsf(tau) + sqrtf(fmaf(tau, tau, 1.0f));
                float tt  = (tau >= 0.0f ? 1.0f : -1.0f) / den;
                c = rsqrtf(fmaf(tt, tt, 1.0f));
                s = tt * c;
            }
            prm[lane] = make_float4(c, s, __int_as_float(p), __int_as_float(q));
        }
        __syncwarp();
        // ---- one-pass tile update: A <- J^T A J  (disjoint 2x2 tiles) ----
        #pragma unroll
        for (int t = 0; t < (NT + 31) / 32; t++) {
            int idx = lane + 32 * t;
            if (idx < NT) {
                int ki = idx / NP, kj = idx - ki * NP;
                float4 pi4 = prm[ki], pj4 = prm[kj];
                float ci = pi4.x, si = pi4.y;
                int pi = __float_as_int(pi4.z), qi = __float_as_int(pi4.w);
                float cj = pj4.x, sj = pj4.y;
                int pj = __float_as_int(pj4.z), qj = __float_as_int(pj4.w);
                float a00 = A[pj * LDC + pi], a01 = A[qj * LDC + pi];
                float a10 = A[pj * LDC + qi], a11 = A[qj * LDC + qi];
                float r00 = fmaf(ci, a00, -si * a10), r10 = fmaf(si, a00, ci * a10);
                float r01 = fmaf(ci, a01, -si * a11), r11 = fmaf(si, a01, ci * a11);
                A[pj * LDC + pi] = fmaf(cj, r00, -sj * r01);
                A[qj * LDC + pi] = fmaf(sj, r00,  cj * r01);
                A[pj * LDC + qi] = fmaf(cj, r10, -sj * r11);
                A[qj * LDC + qi] = fmaf(sj, r10,  cj * r11);
            }
        }
        // ---- V column rotations (independent of A tiles) ----
        #pragma unroll
        for (int t = 0; t < (NP * CH + 31) / 32; t++) {
            int idx = lane + 32 * t;
            if (idx < NP * CH) {
                int k = idx / CH, ch = idx - k * CH;
                float4 pr = prm[k];
                float c = pr.x, s = pr.y;
                int p = __float_as_int(pr.z), q = __float_as_int(pr.w);
                float4 vp = *(reinterpret_cast<float4*>(V + p * LDC) + ch);
                float4 vq = *(reinterpret_cast<float4*>(V + q * LDC) + ch);
                float4 np, nq;
                np.x = fmaf(c, vp.x, -s * vq.x); nq.x = fmaf(s, vp.x, c * vq.x);
                np.y = fmaf(c, vp.y, -s * vq.y); nq.y = fmaf(s, vp.y, c * vq.y);
                np.z = fmaf(c, vp.z, -s * vq.z); nq.z = fmaf(s, vp.z, c * vq.z);
                np.w = fmaf(c, vp.w, -s * vq.w); nq.w = fmaf(s, vp.w, c * vq.w);
                *(reinterpret_cast<float4*>(V + p * LDC) + ch) = np;
                *(reinterpret_cast<float4*>(V + q * LDC) + ch) = nq;
            }
        }
        __syncwarp();
    }
}

// Out[i*N+j] = sum_k V[:,k][i] * fw[k] * V[:,k][j]   (V col-major, LDC) — small kernels only
template<int N>
__device__ __forceinline__ void recompose_cm(const float* V, const float* fw,
                                             float* Out, int lane) {
    #pragma unroll
    for (int t = 0; t < (N * N + 31) / 32; t++) {
        int idx = lane + 32 * t;
        if (idx < N * N) {
            int i = idx / N, j = idx - i * N;
            float acc = 0.0f;
            #pragma unroll
            for (int k = 0; k < N; k++)
                acc = fmaf(V[k * LDC + i] * fw[k], V[k * LDC + j], acc);
            Out[idx] = acc;
        }
    }
}

// ============ K1: per-sample logm(X), per-domain sum of L + counts ============
__global__ void __launch_bounds__(256) k_logsum(const float* __restrict__ X,
                                                const int* __restrict__ dom, int B) {
    __shared__ float acc[NDOM * 400];
    __shared__ float accCnt[NDOM];
    __shared__ WarpWS ws[WPB];
    int tid = threadIdx.x, warp = tid >> 5, lane = tid & 31;
    for (int i = tid; i < NDOM * 400; i += 256) acc[i] = 0.0f;
    if (tid < NDOM) accCnt[tid] = 0.0f;
    __syncthreads();
    WarpWS* w = &ws[warp];
    for (int m = 0; m < MPW; m++) {
        int b = ((int)blockIdx.x * WPB + warp) * MPW + m;
        bool active = (b < B);
        int d = 0;
        float l[20];
        if (active) {
            d = dom[b];
            const float4* Xb4 = (const float4*)(X + (size_t)b * 400);
            for (int idx = lane; idx < 100; idx += 32)
                ((float4*)w->A)[idx] = Xb4[idx];          // symmetric: row-major == col-major
            __syncwarp();
            jacobi_cm<20, SW20>(w, lane);
            if (lane < 20) w->aux[lane] = logf(w->A[lane * LDC + lane]);
            __syncwarp();
            if (lane < 20) {                              // L column 'lane' into registers
                float u[20];
                #pragma unroll
                for (int k = 0; k < 20; k++) u[k] = w->aux[k] * w->V[k * LDC + lane];
                #pragma unroll
                for (int i = 0; i < 20; i++) {
                    float a = 0.0f;
                    #pragma unroll
                    for (int k = 0; k < 20; k++)
                        a = fmaf(w->V[k * LDC + i], u[k], a);   // broadcast LDS
                    l[i] = a;
                }
            }
        }
        for (int t = 0; t < WPB; t++) {                   // deterministic serialized accumulation
            if (warp == t && active && lane < 20) {
                float* dst = acc + d * 400;
                #pragma unroll
                for (int i = 0; i < 20; i++) dst[i * 20 + lane] += l[i];
                if (lane == 0) accCnt[d] += 1.0f;
            }
            __syncthreads();
        }
    }
    for (int idx = tid; idx < NDOM * 400; idx += 256)
        g_partL[(size_t)blockIdx.x * (NDOM * 400) + idx] = acc[idx];
    if (tid < NDOM) g_partCnt[blockIdx.x * NDOM + tid] = accCnt[tid];
}

// ===== K1b: parallel reduce of g_partL over blocks (1600 outputs) =====
__global__ void __launch_bounds__(256) kr_meanL(int NB) {
    int gw = blockIdx.x * 8 + (threadIdx.x >> 5);   // 400 warps
    int lane = threadIdx.x & 31;
    #pragma unroll
    for (int o = 0; o < 4; o++) {
        int out = gw * 4 + o;
        float s = 0.0f;
        for (int b = lane; b < NB; b += 32)
            s += g_partL[(size_t)b * (NDOM * 400) + out];
        #pragma unroll
        for (int off = 16; off; off >>= 1) s += __shfl_down_sync(0xffffffffu, s, off);
        if (lane == 0) g_meanL[out] = s;
    }
}

// ============ K2: counts + Ginv[d] = V e^{-w/2} Vt ============
__global__ void __launch_bounds__(128) k_ginv(int NB) {
    __shared__ WarpWS ws[4];
    int tid = threadIdx.x, warp = tid >> 5, lane = tid & 31;
    int d = warp;
    float csum = 0.0f;
    for (int b = lane; b < NB; b += 32) csum += g_partCnt[b * NDOM + d];
    #pragma unroll
    for (int off = 16; off; off >>= 1) csum += __shfl_down_sync(0xffffffffu, csum, off);
    float cnt = __shfl_sync(0xffffffffu, csum, 0);
    if (lane == 0) g_cnt[d] = cnt;
    WarpWS* w = &ws[warp];
    float inv = 1.0f / cnt;
    for (int idx = lane; idx < 400; idx += 32)
        w->A[idx] = g_meanL[d * 400 + idx] * inv;   // symmetric
    __syncwarp();
    jacobi_cm<20, SW_SMALL>(w, lane);
    if (lane < 20) w->aux[lane] = expf(-0.5f * w->A[lane * LDC + lane]);
    __syncwarp();
    recompose_cm<20>(w->V, w->aux, g_Ginv + d * 400, lane);
}

// ====== K3: M = Gi X Gi, eigh -> store V,logw; per-domain sum ||logM||^2 ======
__global__ void __launch_bounds__(256) k_center(const float* __restrict__ X,
                                                const int* __restrict__ dom, int B) {
    __shared__ float Gi[NDOM * 400];
    __shared__ float nrmAcc[WPB][NDOM];
    __shared__ WarpWS ws[WPB];
    int tid = threadIdx.x, warp = tid >> 5, lane = tid & 31;
    for (int idx = tid; idx < NDOM * 400; idx += 256) Gi[idx] = g_Ginv[idx];
    if (tid < WPB * NDOM) ((float*)nrmAcc)[tid] = 0.0f;
    __syncthreads();
    WarpWS* w = &ws[warp];
    for (int m = 0; m < MPW; m++) {
        int b = ((int)blockIdx.x * WPB + warp) * MPW + m;
        if (b < B) {
            int d = dom[b];
            const float* G = Gi + d * 400;
            const float4* Xb4 = (const float4*)(X + (size_t)b * 400);
            for (int idx = lane; idx < 100; idx += 32)
                ((float4*)w->V)[idx] = Xb4[idx];          // X into V region (broadcast source)
            __syncwarp();
            float g[20], y[20];
            if (lane < 20) {                              // M[:,lane] = G (X (G[:,lane]))
                #pragma unroll
                for (int k = 0; k < 20; k++) g[k] = G[k * 20 + lane];   // coalesced column
                #pragma unroll
                for (int i = 0; i < 20; i++) {
                    float a = 0.0f;
                    #pragma unroll
                    for (int k = 0; k < 20; k++) a = fmaf(w->V[i * 20 + k], g[k], a);
                    y[i] = a;
                }
                #pragma unroll
                for (int i = 0; i < 20; i++) {
                    float a = 0.0f;
                    #pragma unroll
                    for (int k = 0; k < 20; k++) a = fmaf(G[i * 20 + k], y[k], a);
                    g[i] = a;                             // reuse g as result column
                }
            }
            __syncwarp();                                 // all X reads done before jacobi clobbers V
            if (lane < 20) {
                #pragma unroll
                for (int i = 0; i < 20; i++) w->A[lane * LDC + i] = g[i];
            }
            jacobi_cm<20, SW20>(w, lane);                 // internal syncwarp publishes A
            if (lane < 20) w->aux[lane] = logf(w->A[lane * LDC + lane]);
            __syncwarp();
            float* gV = g_V2 + (size_t)b * 400;
            for (int idx = lane; idx < 400; idx += 32) gV[idx] = w->V[idx];  // col-major
            if (lane < 20) g_lw2[(size_t)b * 20 + lane] = w->aux[lane];
            float v = (lane < 20) ? w->aux[lane] * w->aux[lane] : 0.0f;
            #pragma unroll
            for (int off = 16; off; off >>= 1) v += __shfl_down_sync(0xffffffffu, v, off);
            if (lane == 0) nrmAcc[warp][d] += v;
        }
    }
    __syncthreads();
    if (tid == 0) {
        float sums[NDOM] = {0.f, 0.f, 0.f, 0.f};
        for (int t = 0; t < WPB; t++)
            for (int d = 0; d < NDOM; d++) sums[d] += nrmAcc[t][d];
        for (int d = 0; d < NDOM; d++) g_partN[blockIdx.x * NDOM + d] = sums[d];
    }
}

// ============ K4: scale[d] = s / sqrt(sig2 + eps) ============
__global__ void __launch_bounds__(128) k_scale(const float* __restrict__ sptr, int NB) {
    int warp = threadIdx.x >> 5, lane = threadIdx.x & 31;
    int d = warp;
    float nsum = 0.0f;
    for (int b = lane; b < NB; b += 32) nsum += g_partN[b * NDOM + d];
    #pragma unroll
    for (int off = 16; off; off >>= 1) nsum += __shfl_down_sync(0xffffffffu, nsum, off);
    if (lane == 0) {
        float sig2 = nsum / g_cnt[d];
        g_scale[d] = sptr[0] / sqrtf(sig2 + EPS_VAR_F);
    }
}

// ====== K5: Xn via eigenbasis reuse, Y = Wt Xn W, store Y, sum logm(Y) ======
__global__ void __launch_bounds__(256) k_bimap(const float* __restrict__ Wb,
                                               const int* __restrict__ dom, int B) {
    __shared__ float W[300];
    __shared__ float accLY[225];
    __shared__ WarpWS ws[WPB];
    int tid = threadIdx.x, warp = tid >> 5, lane = tid & 31;
    for (int i = tid; i < 300; i += 256) W[i] = Wb[i];
    for (int i = tid; i < 225; i += 256) accLY[i] = 0.0f;
    __syncthreads();
    WarpWS* w = &ws[warp];
    for (int m = 0; m < MPW; m++) {
        int b = ((int)blockIdx.x * WPB + warp) * MPW + m;
        bool active = (b < B);
        float l[15];
        if (active) {
            int d = dom[b];
            float sc = g_scale[d];
            const float* gV = g_V2 + (size_t)b * 400;
            float c[15];
            if (lane < 20) {
                // z = V[:,lane] * e^{sc*lw[lane]/2}  (Xn = Z Z^T)
                float ej = expf(0.5f * sc * g_lw2[(size_t)b * 20 + lane]);
                float z[20];
                const float4* col4 = (const float4*)(gV + lane * 20);
                #pragma unroll
                for (int t = 0; t < 5; t++) {
                    float4 v = col4[t];
                    z[4 * t + 0] = v.x * ej; z[4 * t + 1] = v.y * ej;
                    z[4 * t + 2] = v.z * ej; z[4 * t + 3] = v.w * ej;
                }
                // C[o][lane] = sum_i W[i][o] * z[i]
                #pragma unroll
                for (int o = 0; o < 15; o++) {
                    float a = 0.0f;
                    #pragma unroll
                    for (int i = 0; i < 20; i++) a = fmaf(W[i * 15 + o], z[i], a);
                    c[o] = a;
                }
            }
            __syncwarp();
            if (lane < 20) {
                #pragma unroll
                for (int o = 0; o < 15; o++) w->V[o * 20 + lane] = c[o];  // C row-major in V
            }
            __syncwarp();
            float yv[15];
            if (lane < 15) {                       // Y[:,lane] = C C^T column
                float cp[20];
                #pragma unroll
                for (int k = 0; k < 20; k++) cp[k] = w->V[lane * 20 + k];
                #pragma unroll
                for (int o = 0; o < 15; o++) {
                    float a = 0.0f;
                    #pragma unroll
                    for (int k = 0; k < 20; k++) a = fmaf(w->V[o * 20 + k], cp[k], a);
                    yv[o] = a;
                }
            }
            __syncwarp();                          // all C reads done before zero/jacobi
            for (int idx = lane; idx < 320; idx += 32) w->A[idx] = 0.0f;
            __syncwarp();
            if (lane < 15) {
                float* gY = g_Y + (size_t)b * 225;
                #pragma unroll
                for (int o = 0; o < 15; o++) {
                    w->A[lane * LDC + o] = yv[o];
                    gY[lane * 15 + o] = yv[o];     // symmetric
                }
            }
            jacobi_cm<15, SW15>(w, lane);
            if (lane < 15) w->aux[lane] = logf(w->A[lane * LDC + lane]);
            __syncwarp();
            if (lane < 15) {
                float u[15];
                #pragma unroll
                for (int k = 0; k < 15; k++) u[k] = w->aux[k] * w->V[k * LDC + lane];
                #pragma unroll
                for (int i = 0; i < 15; i++) {
                    float a = 0.0f;
                    #pragma unroll
                    for (int k = 0; k < 15; k++) a = fmaf(w->V[k * LDC + i], u[k], a);
                    l[i] = a;
                }
            }
        }
        for (int t = 0; t < WPB; t++) {
            if (warp == t && active && lane < 15) {
                #pragma unroll
                for (int i = 0; i < 15; i++) accLY[i * 15 + lane] += l[i];
            }
            __syncthreads();
        }
    }
    for (int idx = tid; idx < 225; idx += 256)
        g_partLY[(size_t)blockIdx.x * 225 + idx] = accLY[idx];
}

// ============ K6: meanLY -> Gb = V e^{-w/2} Vt ============
__global__ void __launch_bounds__(256) k_gb(int B, int NB) {
    __shared__ float meanLY[225];
    __shared__ WarpWS ws0;
    int tid = threadIdx.x, warp = tid >> 5, lane = tid & 31;
    float invB = 1.0f / (float)B;
    for (int out = warp; out < 225; out += 8) {
        float s = 0.0f;
        for (int b = lane; b < NB; b += 32) s += g_partLY[(size_t)b * 225 + out];
        #pragma unroll
        for (int off = 16; off; off >>= 1) s += __shfl_down_sync(0xffffffffu, s, off);
        if (lane == 0) meanLY[out] = s * invB;
    }
    __syncthreads();
    if (warp == 0) {
        for (int idx = lane; idx < 320; idx += 32) ws0.A[idx] = 0.0f;
        __syncwarp();
        for (int idx = lane; idx < 225; idx += 32) {
            int i = idx / 15, j = idx - i * 15;
            ws0.A[j * LDC + i] = meanLY[idx];
        }
        __syncwarp();
        jacobi_cm<15, SW_SMALL>(&ws0, lane);
        if (lane < 15) ws0.aux[lane] = expf(-0.5f * ws0.A[lane * LDC + lane]);
        __syncwarp();
        recompose_cm<15>(ws0.V, ws0.aux, g_Gb, lane);
    }
}

// ====== K7: Yn = Gb Y Gb, eigh, Lf = V log(max(w,eps)) Vt, vec, classifier ======
__global__ void __launch_bounds__(256) k_head(const float* __restrict__ Wl,
                                              float* __restrict__ out, int B) {
    __shared__ float Gb[225];
    __shared__ float W[480];
    __shared__ WarpWS ws[WPB];
    int tid = threadIdx.x, warp = tid >> 5, lane = tid & 31;
    for (int i = tid; i < 225; i += 256) Gb[i] = g_Gb[i];
    for (int i = tid; i < 480; i += 256) W[i] = Wl[i];
    __syncthreads();
    WarpWS* w = &ws[warp];
    for (int m = 0; m < MPW; m++) {
        int b = ((int)blockIdx.x * WPB + warp) * MPW + m;
        if (b >= B) continue;
        const float* gY = g_Y + (size_t)b * 225;
        for (int idx = lane; idx < 225; idx += 32) w->V[idx] = gY[idx];  // Y (broadcast source)
        __syncwarp();
        float g[15], y[15];
        if (lane < 15) {                          // M[:,lane] = Gb (Y (Gb[:,lane]))
            #pragma unroll
            for (int k = 0; k < 15; k++) g[k] = Gb[k * 15 + lane];
            #pragma unroll
            for (int i = 0; i < 15; i++) {
                float a = 0.0f;
                #pragma unroll
                for (int k = 0; k < 15; k++) a = fmaf(w->V[i * 15 + k], g[k], a);
                y[i] = a;
            }
            #pragma unroll
            for (int i = 0; i < 15; i++) {
                float a = 0.0f;
                #pragma unroll
                for (int k = 0; k < 15; k++) a = fmaf(Gb[i * 15 + k], y[k], a);
                g[i] = a;
            }
        }
        __syncwarp();                             // Y reads done before jacobi clobbers V
        for (int idx = lane; idx < 320; idx += 32) w->A[idx] = 0.0f;
        __syncwarp();
        if (lane < 15) {
            #pragma unroll
            for (int i = 0; i < 15; i++) w->A[lane * LDC + i] = g[i];
        }
        jacobi_cm<15, SW15>(w, lane);
        if (lane < 15) w->aux[lane] = logf(fmaxf(w->A[lane * LDC + lane], EPS_REEIG_F));
        __syncwarp();
        // vec + classifier fused
        float o0 = 0.f, o1 = 0.f, o2 = 0.f, o3 = 0.f;
        for (int idx = lane; idx < 120; idx += 32) {
            int i, j;
            float coef;
            if (idx < 15) { i = idx; j = idx; coef = 1.0f; }
            else {
                int t = idx - 15;
                int ii = 0;
                while (t >= 14 - ii) { t -= 14 - ii; ii++; }
                i = ii; j = ii + 1 + t; coef = SQRT2F;
            }
            float lf = 0.0f;
            #pragma unroll
            for (int k = 0; k < 15; k++)
                lf = fmaf(w->V[k * LDC + i] * w->aux[k], w->V[k * LDC + j], lf);
            float v = coef * lf;
            o0 = fmaf(v, W[0 * 120 + idx], o0);
            o1 = fmaf(v, W[1 * 120 + idx], o1);
            o2 = fmaf(v, W[2 * 120 + idx], o2);
            o3 = fmaf(v, W[3 * 120 + idx], o3);
        }
        #pragma unroll
        for (int off = 16; off; off >>= 1) {
            o0 += __shfl_down_sync(0xffffffffu, o0, off);
            o1 += __shfl_down_sync(0xffffffffu, o1, off);
            o2 += __shfl_down_sync(0xffffffffu, o2, off);
            o3 += __shfl_down_sync(0xffffffffu, o3, off);
        }
        if (lane == 0) {
            float* ob = out + (size_t)b * 4;
            ob[0] = o0; ob[1] = o1; ob[2] = o2; ob[3] = o3;
        }
    }
}

extern "C" void kernel_launch(void* const* d_in, const int* in_sizes, int n_in,
                              void* d_out, int out_size) {
    const float* X   = (const float*)d_in[0];
    const int*   dom = (const int*)d_in[1];
    const float* s   = (const float*)d_in[2];
    const float* Wb  = (const float*)d_in[3];
    const float* Wl  = (const float*)d_in[4];
    float* out = (float*)d_out;
    int B = in_sizes[0] / 400;
    if (B > MAXB) B = MAXB;
    int NB = (B + MPB - 1) / MPB;
    if (NB > NB_MAX) NB = NB_MAX;

    k_logsum<<<NB, 256>>>(X, dom, B);
    kr_meanL<<<50, 256>>>(NB);
    k_ginv<<<1, 128>>>(NB);
    k_center<<<NB, 256>>>(X, dom, B);
    k_scale<<<1, 128>>>(s, NB);
    k_bimap<<<NB, 256>>>(Wb, dom, B);
    k_gb<<<1, 256>>>(B, NB);
    k_head<<<NB, 256>>>(Wl, out, B);
}